// round 1
// baseline (speedup 1.0000x reference)
#include <cuda_runtime.h>
#include <math.h>

#define NTOK_MAX 8192
#define NE 64

// 128 MB scratch for the intermediate activation h = gelu(up(x))  [N, 4096]
__device__ float g_h[(size_t)NTOK_MAX * 4096];

__device__ __forceinline__ float gelu_erf(float v) {
    // exact erf-based gelu: v * Phi(v)
    return v * normcdff(v);
}

// ---------------------------------------------------------------------------
// Up kernel: router(1024->64) + top2 softmax + Y = A(64x32) X(32x32) B^T(64x32)
// one token per block, 256 threads
// ---------------------------------------------------------------------------
__global__ __launch_bounds__(256) void kmoe_up_kernel(
    const float* __restrict__ x,        // [N,1024]
    const float* __restrict__ W_up,     // [64,1024]
    const float* __restrict__ A_up,     // [64,64,32]
    const float* __restrict__ B_up,     // [64,64,32]
    const float* __restrict__ scale_up, // [1]
    const float* __restrict__ bias_up,  // [4096]
    float* __restrict__ h_out)          // [N,4096]
{
    __shared__ float sX[32][32];       // natural: only broadcast reads
    __shared__ float sA[64][33];       // padded: per-lane reads sA[o][i]
    __shared__ float sT[64][33];       // padded: per-lane reads sT[o][j]
    __shared__ float sB[64 * 32];      // natural: only broadcast reads
    __shared__ float sLogit[NE];
    __shared__ float sProb[2];
    __shared__ int   sIdx[2];

    const int t    = blockIdx.x;
    const int tid  = threadIdx.x;
    const int lane = tid & 31;
    const int warp = tid >> 5;

    const float* xt = x + (size_t)t * 1024;

    // ---- stage x into smem (32x32) ----
    {
        float4 v = __ldg(((const float4*)xt) + tid);   // elements 4*tid..4*tid+3
        int base = 4 * tid;
        int r = base >> 5, c = base & 31;
        sX[r][c]     = v.x;
        sX[r][c + 1] = v.y;
        sX[r][c + 2] = v.z;
        sX[r][c + 3] = v.w;
    }

    // ---- router: warp w handles experts 8w..8w+7 ----
    {
        float acc[8];
        #pragma unroll
        for (int e = 0; e < 8; e++) acc[e] = 0.f;
        const float4* x4 = (const float4*)xt;
        #pragma unroll
        for (int m = 0; m < 8; m++) {
            float4 xv = __ldg(&x4[lane + 32 * m]);
            #pragma unroll
            for (int e = 0; e < 8; e++) {
                const float4* w4 = (const float4*)(W_up + (size_t)(8 * warp + e) * 1024);
                float4 wv = __ldg(&w4[lane + 32 * m]);
                acc[e] += xv.x * wv.x + xv.y * wv.y + xv.z * wv.z + xv.w * wv.w;
            }
        }
        #pragma unroll
        for (int e = 0; e < 8; e++) {
            float v = acc[e];
            v += __shfl_xor_sync(0xffffffffu, v, 16);
            v += __shfl_xor_sync(0xffffffffu, v, 8);
            v += __shfl_xor_sync(0xffffffffu, v, 4);
            v += __shfl_xor_sync(0xffffffffu, v, 2);
            v += __shfl_xor_sync(0xffffffffu, v, 1);
            if (lane == 0) sLogit[8 * warp + e] = v;
        }
    }
    __syncthreads();

    // ---- top-2 + softmax (single thread; trivial cost) ----
    if (tid == 0) {
        int   i1 = 0;
        float v1 = sLogit[0];
        for (int e = 1; e < NE; e++) {
            float v = sLogit[e];
            if (v > v1) { v1 = v; i1 = e; }
        }
        int   i2 = -1;
        float v2 = -INFINITY;
        for (int e = 0; e < NE; e++) {
            if (e == i1) continue;
            float v = sLogit[e];
            if (v > v2) { v2 = v; i2 = e; }
        }
        float p1 = 1.f / (1.f + expf(v2 - v1));
        sIdx[0]  = i1;
        sIdx[1]  = i2;
        sProb[0] = p1;
        sProb[1] = 1.f - p1;
    }
    __syncthreads();

    // thread mapping: o = tid&63 (consecutive per warp), sub = tid>>6 (warp-uniform)
    const int o   = tid & 63;
    const int sub = tid >> 6;    // 0..3
    const int jb  = sub * 8;     // T phase: 8 j's
    const int pb  = sub * 16;    // Y phase: 16 p's

    float out_acc[16];
    #pragma unroll
    for (int p = 0; p < 16; p++) out_acc[p] = 0.f;

    #pragma unroll
    for (int k = 0; k < 2; k++) {
        const int   e    = sIdx[k];
        const float prob = sProb[k];

        // stage A_up[e] (64x32) into padded sA
        {
            const float4* a4 = (const float4*)(A_up + (size_t)e * 2048);
            #pragma unroll
            for (int m = 0; m < 2; m++) {
                float4 v = __ldg(&a4[tid + 256 * m]);
                int base = 4 * (tid + 256 * m);
                int r = base >> 5, c = base & 31;
                sA[r][c]     = v.x;
                sA[r][c + 1] = v.y;
                sA[r][c + 2] = v.z;
                sA[r][c + 3] = v.w;
            }
        }
        // stage B_up[e] (64x32) natural layout (float4 direct)
        {
            const float4* b4  = (const float4*)(B_up + (size_t)e * 2048);
            float4*       sB4 = (float4*)sB;
            #pragma unroll
            for (int m = 0; m < 2; m++) sB4[tid + 256 * m] = __ldg(&b4[tid + 256 * m]);
        }
        __syncthreads();

        // T[o][jb+jj] = sum_i A[o][i] * X[i][jb+jj]
        {
            float tacc[8];
            #pragma unroll
            for (int jj = 0; jj < 8; jj++) tacc[jj] = 0.f;
            #pragma unroll
            for (int i = 0; i < 32; i++) {
                float a = sA[o][i];
                const float2* xrow = (const float2*)&sX[i][jb];  // warp-uniform -> broadcast
                #pragma unroll
                for (int jj = 0; jj < 4; jj++) {
                    float2 xv = xrow[jj];
                    tacc[2 * jj]     += a * xv.x;
                    tacc[2 * jj + 1] += a * xv.y;
                }
            }
            #pragma unroll
            for (int jj = 0; jj < 8; jj++) sT[o][jb + jj] = tacc[jj];
        }
        __syncthreads();

        // Y[o][pb+pp] = sum_j T[o][j] * B[pb+pp][j]
        {
            float yk[16];
            #pragma unroll
            for (int p = 0; p < 16; p++) yk[p] = 0.f;
            #pragma unroll
            for (int j = 0; j < 32; j += 2) {
                float t0 = sT[o][j];
                float t1 = sT[o][j + 1];
                #pragma unroll
                for (int pp = 0; pp < 16; pp++) {
                    float2 bv = *(const float2*)&sB[(pb + pp) * 32 + j];  // warp-uniform
                    yk[pp] += t0 * bv.x + t1 * bv.y;
                }
            }
            #pragma unroll
            for (int pp = 0; pp < 16; pp++) out_acc[pp] += prob * yk[pp];
        }
        __syncthreads();  // before re-staging sA/sB/sT for next k
    }

    // ---- epilogue: scale, bias, gelu, store 16 contiguous floats ----
    {
        const float  scale = __ldg(scale_up);
        float*       hrow  = h_out + (size_t)t * 4096 + o * 64 + pb;
        const float* brow  = bias_up + o * 64 + pb;
        #pragma unroll
        for (int pp = 0; pp < 16; pp += 4) {
            float4 bv = __ldg((const float4*)(brow + pp));
            float4 r;
            r.x = gelu_erf(out_acc[pp]     * scale + bv.x);
            r.y = gelu_erf(out_acc[pp + 1] * scale + bv.y);
            r.z = gelu_erf(out_acc[pp + 2] * scale + bv.z);
            r.w = gelu_erf(out_acc[pp + 3] * scale + bv.w);
            *(float4*)(hrow + pp) = r;
        }
    }
}

// ---------------------------------------------------------------------------
// Down kernel: router(4096->64) + top2 softmax + Y = A(32x64) H(64x64) B^T(32x64)
// one token per block, 256 threads
// ---------------------------------------------------------------------------
__global__ __launch_bounds__(256) void kmoe_down_kernel(
    const float* __restrict__ h,          // [N,4096]
    const float* __restrict__ W_down,     // [64,4096]
    const float* __restrict__ A_down,     // [64,32,64]
    const float* __restrict__ B_down,     // [64,32,64]
    const float* __restrict__ scale_down, // [1]
    const float* __restrict__ bias_down,  // [1024]
    float* __restrict__ out)              // [N,1024]
{
    __shared__ float sH[64 * 64];      // 16KB, natural: broadcast + float4 reads
    __shared__ float sA[32][65];       // padded
    __shared__ float sT[32][65];       // padded
    __shared__ float sB[32 * 64];      // natural: broadcast reads
    __shared__ float sLogit[NE];
    __shared__ float sProb[2];
    __shared__ int   sIdx[2];

    const int t    = blockIdx.x;
    const int tid  = threadIdx.x;
    const int lane = tid & 31;
    const int warp = tid >> 5;

    // ---- stage h into smem ----
    {
        const float4* h4  = (const float4*)(h + (size_t)t * 4096);
        float4*       sH4 = (float4*)sH;
        #pragma unroll
        for (int m = 0; m < 4; m++) sH4[tid + 256 * m] = __ldg(&h4[tid + 256 * m]);
    }
    __syncthreads();

    // ---- router: warp w handles experts 8w..8w+7 over 4096 dims ----
    {
        float acc[8];
        #pragma unroll
        for (int e = 0; e < 8; e++) acc[e] = 0.f;
        const float4* sH4 = (const float4*)sH;
        for (int m = 0; m < 32; m++) {
            float4 xv = sH4[lane + 32 * m];
            #pragma unroll
            for (int e = 0; e < 8; e++) {
                const float4* w4 = (const float4*)(W_down + (size_t)(8 * warp + e) * 4096);
                float4 wv = __ldg(&w4[lane + 32 * m]);
                acc[e] += xv.x * wv.x + xv.y * wv.y + xv.z * wv.z + xv.w * wv.w;
            }
        }
        #pragma unroll
        for (int e = 0; e < 8; e++) {
            float v = acc[e];
            v += __shfl_xor_sync(0xffffffffu, v, 16);
            v += __shfl_xor_sync(0xffffffffu, v, 8);
            v += __shfl_xor_sync(0xffffffffu, v, 4);
            v += __shfl_xor_sync(0xffffffffu, v, 2);
            v += __shfl_xor_sync(0xffffffffu, v, 1);
            if (lane == 0) sLogit[8 * warp + e] = v;
        }
    }
    __syncthreads();

    if (tid == 0) {
        int   i1 = 0;
        float v1 = sLogit[0];
        for (int e = 1; e < NE; e++) {
            float v = sLogit[e];
            if (v > v1) { v1 = v; i1 = e; }
        }
        int   i2 = -1;
        float v2 = -INFINITY;
        for (int e = 0; e < NE; e++) {
            if (e == i1) continue;
            float v = sLogit[e];
            if (v > v2) { v2 = v; i2 = e; }
        }
        float p1 = 1.f / (1.f + expf(v2 - v1));
        sIdx[0]  = i1;
        sIdx[1]  = i2;
        sProb[0] = p1;
        sProb[1] = 1.f - p1;
    }
    __syncthreads();

    // mapping: o = tid&31 (o == lane, consecutive), sub = tid>>5 (warp-uniform)
    const int o   = tid & 31;
    const int sub = tid >> 5;   // 0..7
    const int jb  = sub * 8;    // T phase: 8 j's
    const int pb  = sub * 4;    // Y phase: 4 p's

    float out_acc[4];
    #pragma unroll
    for (int p = 0; p < 4; p++) out_acc[p] = 0.f;

    #pragma unroll
    for (int k = 0; k < 2; k++) {
        const int   e    = sIdx[k];
        const float prob = sProb[k];

        // stage A_down[e] (32x64) into padded sA
        {
            const float4* a4 = (const float4*)(A_down + (size_t)e * 2048);
            #pragma unroll
            for (int m = 0; m < 2; m++) {
                float4 v = __ldg(&a4[tid + 256 * m]);
                int base = 4 * (tid + 256 * m);
                int r = base >> 6, c = base & 63;
                sA[r][c]     = v.x;
                sA[r][c + 1] = v.y;
                sA[r][c + 2] = v.z;
                sA[r][c + 3] = v.w;
            }
        }
        // stage B_down[e] (32x64) natural
        {
            const float4* b4  = (const float4*)(B_down + (size_t)e * 2048);
            float4*       sB4 = (float4*)sB;
            #pragma unroll
            for (int m = 0; m < 2; m++) sB4[tid + 256 * m] = __ldg(&b4[tid + 256 * m]);
        }
        __syncthreads();

        // T[o][jb+jj] = sum_{i<64} A[o][i] * H[i][jb+jj]
        {
            float tacc[8];
            #pragma unroll
            for (int jj = 0; jj < 8; jj++) tacc[jj] = 0.f;
            #pragma unroll
            for (int i = 0; i < 64; i++) {
                float a = sA[o][i];
                const float2* hrow = (const float2*)&sH[i * 64 + jb];  // warp-uniform
                #pragma unroll
                for (int jj = 0; jj < 4; jj++) {
                    float2 hv = hrow[jj];
                    tacc[2 * jj]     += a * hv.x;
                    tacc[2 * jj + 1] += a * hv.y;
                }
            }
            #pragma unroll
            for (int jj = 0; jj < 8; jj++) sT[o][jb + jj] = tacc[jj];
        }
        __syncthreads();

        // Y[o][pb+pp] = sum_{j<64} T[o][j] * B[pb+pp][j]
        {
            float yk[4];
            #pragma unroll
            for (int p = 0; p < 4; p++) yk[p] = 0.f;
            #pragma unroll
            for (int j = 0; j < 64; j += 2) {
                float t0 = sT[o][j];
                float t1 = sT[o][j + 1];
                #pragma unroll
                for (int pp = 0; pp < 4; pp++) {
                    float2 bv = *(const float2*)&sB[(pb + pp) * 64 + j];  // warp-uniform
                    yk[pp] += t0 * bv.x + t1 * bv.y;
                }
            }
            #pragma unroll
            for (int pp = 0; pp < 4; pp++) out_acc[pp] += prob * yk[pp];
        }
        __syncthreads();
    }

    // ---- epilogue: scale, bias, store 4 contiguous floats ----
    {
        const float scale = __ldg(scale_down);
        float4 bv = __ldg((const float4*)(bias_down + o * 32 + pb));
        float4 r;
        r.x = out_acc[0] * scale + bv.x;
        r.y = out_acc[1] * scale + bv.y;
        r.z = out_acc[2] * scale + bv.z;
        r.w = out_acc[3] * scale + bv.w;
        *(float4*)(out + (size_t)t * 1024 + o * 32 + pb) = r;
    }
}

// ---------------------------------------------------------------------------
extern "C" void kernel_launch(void* const* d_in, const int* in_sizes, int n_in,
                              void* d_out, int out_size) {
    const float* x          = (const float*)d_in[0];
    const float* W_up       = (const float*)d_in[1];
    const float* A_up       = (const float*)d_in[2];
    const float* B_up       = (const float*)d_in[3];
    const float* scale_up   = (const float*)d_in[4];
    const float* bias_up    = (const float*)d_in[5];
    const float* W_down     = (const float*)d_in[6];
    const float* A_down     = (const float*)d_in[7];
    const float* B_down     = (const float*)d_in[8];
    const float* scale_down = (const float*)d_in[9];
    const float* bias_down  = (const float*)d_in[10];
    float*       out        = (float*)d_out;

    const int n_tok = in_sizes[0] / 1024;   // 8192

    float* h_ptr = nullptr;
    cudaGetSymbolAddress((void**)&h_ptr, g_h);

    kmoe_up_kernel<<<n_tok, 256>>>(x, W_up, A_up, B_up, scale_up, bias_up, h_ptr);
    kmoe_down_kernel<<<n_tok, 256>>>(h_ptr, W_down, A_down, B_down, scale_down,
                                     bias_down, out);
}

// round 2
// speedup vs baseline: 1.3071x; 1.3071x over previous
#include <cuda_runtime.h>
#include <math.h>

#define NTOK   8192
#define NPAIR  (NTOK * 2)
#define NE     64
#define TPB    16
#define MAXCHUNK (NPAIR / TPB + NE)   // 1088

// ---- scratch (device globals; no allocs allowed) ----
__device__ float g_h[(size_t)NTOK * 4096];        // 134 MB
__device__ float g_yup[(size_t)NPAIR * 4096];     // 268 MB
__device__ float g_ydown[(size_t)NPAIR * 1024];   // 67 MB
__device__ float g_logits[(size_t)NTOK * NE];     // 2 MB
__device__ float g_prob[NPAIR];
__device__ int   g_cnt[NE];
__device__ int   g_list[NE * NPAIR];              // 4 MB
__device__ int2  g_chunk[MAXCHUNK];
__device__ int   g_nchunks;

__device__ __forceinline__ float gelu_erf(float v) { return v * normcdff(v); }

// ---------------------------------------------------------------------------
// Router GEMM: logits[M,64] = X[M,K] * W[64,K]^T.  64-token M tiles, 256 thr.
// 4x4 register tiles; smem tiles stored K-major (transposed) so compute does
// 2 LDS.128 per 16 FFMA.
// ---------------------------------------------------------------------------
template<int K>
__global__ __launch_bounds__(256) void router_gemm(
    const float* __restrict__ X, const float* __restrict__ W)
{
    __shared__ float sXT[32][68];   // [k][m]
    __shared__ float sWT[32][68];   // [k][e]
    const int tid = threadIdx.x;
    if (blockIdx.x == 0 && tid < NE) g_cnt[tid] = 0;   // reset counters for top2

    const int m0 = blockIdx.x * 64;

    // staging decomposition: float4 id f in [0,512): row = f>>3, kcol = (f&7)*4
    const int f0 = tid, f1 = tid + 256;
    const int r0 = f0 >> 3, c0 = (f0 & 7) * 4;
    const int r1 = f1 >> 3, c1 = (f1 & 7) * 4;

    const int mq = (tid & 15) * 4;   // 4 tokens
    const int eq = (tid >> 4) * 4;   // 4 experts

    float acc[4][4];
    #pragma unroll
    for (int i = 0; i < 4; i++)
        #pragma unroll
        for (int j = 0; j < 4; j++) acc[i][j] = 0.f;

    float4 rx0 = *(const float4*)&X[(size_t)(m0 + r0) * K + c0];
    float4 rx1 = *(const float4*)&X[(size_t)(m0 + r1) * K + c1];
    float4 rw0 = *(const float4*)&W[(size_t)r0 * K + c0];
    float4 rw1 = *(const float4*)&W[(size_t)r1 * K + c1];

    for (int kc = 0; kc < K; kc += 32) {
        sXT[c0+0][r0]=rx0.x; sXT[c0+1][r0]=rx0.y; sXT[c0+2][r0]=rx0.z; sXT[c0+3][r0]=rx0.w;
        sXT[c1+0][r1]=rx1.x; sXT[c1+1][r1]=rx1.y; sXT[c1+2][r1]=rx1.z; sXT[c1+3][r1]=rx1.w;
        sWT[c0+0][r0]=rw0.x; sWT[c0+1][r0]=rw0.y; sWT[c0+2][r0]=rw0.z; sWT[c0+3][r0]=rw0.w;
        sWT[c1+0][r1]=rw1.x; sWT[c1+1][r1]=rw1.y; sWT[c1+2][r1]=rw1.z; sWT[c1+3][r1]=rw1.w;
        __syncthreads();
        if (kc + 32 < K) {
            rx0 = *(const float4*)&X[(size_t)(m0 + r0) * K + kc + 32 + c0];
            rx1 = *(const float4*)&X[(size_t)(m0 + r1) * K + kc + 32 + c1];
            rw0 = *(const float4*)&W[(size_t)r0 * K + kc + 32 + c0];
            rw1 = *(const float4*)&W[(size_t)r1 * K + kc + 32 + c1];
        }
        #pragma unroll
        for (int k = 0; k < 32; k++) {
            float4 xv = *(const float4*)&sXT[k][mq];
            float4 wv = *(const float4*)&sWT[k][eq];
            acc[0][0] += xv.x*wv.x; acc[0][1] += xv.x*wv.y; acc[0][2] += xv.x*wv.z; acc[0][3] += xv.x*wv.w;
            acc[1][0] += xv.y*wv.x; acc[1][1] += xv.y*wv.y; acc[1][2] += xv.y*wv.z; acc[1][3] += xv.y*wv.w;
            acc[2][0] += xv.z*wv.x; acc[2][1] += xv.z*wv.y; acc[2][2] += xv.z*wv.z; acc[2][3] += xv.z*wv.w;
            acc[3][0] += xv.w*wv.x; acc[3][1] += xv.w*wv.y; acc[3][2] += xv.w*wv.z; acc[3][3] += xv.w*wv.w;
        }
        __syncthreads();
    }
    #pragma unroll
    for (int i = 0; i < 4; i++) {
        float4 v = make_float4(acc[i][0], acc[i][1], acc[i][2], acc[i][3]);
        *(float4*)&g_logits[(size_t)(m0 + mq + i) * NE + eq] = v;
    }
}

// ---------------------------------------------------------------------------
// Top-2 + softmax + per-expert list build.  One warp per token.
// ---------------------------------------------------------------------------
__global__ __launch_bounds__(256) void top2_kernel()
{
    const int t    = blockIdx.x * 8 + (threadIdx.x >> 5);
    const int lane = threadIdx.x & 31;
    const float* lg = &g_logits[(size_t)t * NE];
    float v0 = lg[lane], v1 = lg[lane + 32];

    float m1; int i1;
    if (v0 >= v1) { m1 = v0; i1 = lane; } else { m1 = v1; i1 = lane + 32; }
    #pragma unroll
    for (int off = 16; off > 0; off >>= 1) {
        float om = __shfl_xor_sync(0xffffffffu, m1, off);
        int   oi = __shfl_xor_sync(0xffffffffu, i1, off);
        if (om > m1 || (om == m1 && oi < i1)) { m1 = om; i1 = oi; }
    }
    float c0 = (lane == i1)      ? -INFINITY : v0;
    float c1 = (lane + 32 == i1) ? -INFINITY : v1;
    float m2; int i2;
    if (c0 >= c1) { m2 = c0; i2 = lane; } else { m2 = c1; i2 = lane + 32; }
    #pragma unroll
    for (int off = 16; off > 0; off >>= 1) {
        float om = __shfl_xor_sync(0xffffffffu, m2, off);
        int   oi = __shfl_xor_sync(0xffffffffu, i2, off);
        if (om > m2 || (om == m2 && oi < i2)) { m2 = om; i2 = oi; }
    }
    if (lane == 0) {
        float p1 = 1.f / (1.f + expf(m2 - m1));
        g_prob[2 * t]     = p1;
        g_prob[2 * t + 1] = 1.f - p1;
        int pos = atomicAdd(&g_cnt[i1], 1);
        g_list[i1 * NPAIR + pos] = 2 * t;
        pos = atomicAdd(&g_cnt[i2], 1);
        g_list[i2 * NPAIR + pos] = 2 * t + 1;
    }
}

// ---------------------------------------------------------------------------
// Chunk map: block b of the bilinear kernels -> (expert, start offset)
// ---------------------------------------------------------------------------
__global__ void prefix_kernel()
{
    __shared__ int s_c[NE];
    __shared__ int s_off[NE];
    const int e = threadIdx.x;     // 64 threads
    int c = (g_cnt[e] + TPB - 1) / TPB;
    s_c[e] = c;
    __syncthreads();
    if (e == 0) {
        int s = 0;
        for (int i = 0; i < NE; i++) { s_off[i] = s; s += s_c[i]; }
        g_nchunks = s;
    }
    __syncthreads();
    int o = s_off[e];
    for (int i = 0; i < c; i++)
        g_chunk[o + i] = make_int2(e, i * TPB);
}

// ---------------------------------------------------------------------------
// Up bilinear: per pair  T(64x32) = A_e(64x32) X(32x32);  Y(64x64) = T B_e^T
// A/B staged transposed once per 16 pairs.  256 threads.
// ---------------------------------------------------------------------------
__global__ __launch_bounds__(256) void bilinear_up(
    const float* __restrict__ x, const float* __restrict__ A, const float* __restrict__ B)
{
    const int b = blockIdx.x;
    if (b >= g_nchunks) return;
    const int2 ch   = g_chunk[b];
    const int e     = ch.x;
    const int start = ch.y;
    const int cnt   = g_cnt[e];
    const int tid   = threadIdx.x;

    __shared__ float sAT[32][66];   // [i][o]
    __shared__ float sBT[32][66];   // [j][p]
    __shared__ float sX [32][68];   // [i][j]
    __shared__ float sTT[32][68];   // [j][o]

    {   // stage A [64][32] -> sAT, B [64][32] -> sBT (transposed)
        const float4* a4 = (const float4*)(A + (size_t)e * 2048);
        const float4* b4 = (const float4*)(B + (size_t)e * 2048);
        #pragma unroll
        for (int rr = 0; rr < 2; rr++) {
            int f   = tid + 256 * rr;
            int row = f >> 3;            // o or p
            int col = (f & 7) * 4;       // i or j
            float4 av = a4[f];
            sAT[col+0][row]=av.x; sAT[col+1][row]=av.y; sAT[col+2][row]=av.z; sAT[col+3][row]=av.w;
            float4 bv = b4[f];
            sBT[col+0][row]=bv.x; sBT[col+1][row]=bv.y; sBT[col+2][row]=bv.z; sBT[col+3][row]=bv.w;
        }
    }

    const int op = tid & 31;       // T: o pair base 2*op
    const int jq = tid >> 5;       // T: j base 4*jq  (warp-uniform)
    const int oq = tid >> 5;       // Y: o base 8*oq  (warp-uniform)
    const int pp = tid & 31;       // Y: p base 2*pp
    const int xi = tid >> 3;       // X stage row
    const int xj = (tid & 7) * 4;  // X stage col

    __syncthreads();

    for (int u = 0; u < TPB; u++) {
        int pi = start + u;
        if (pi >= cnt) break;                      // block-uniform
        int pair = g_list[e * NPAIR + pi];
        int t    = pair >> 1;

        float4 xv = *(const float4*)&x[(size_t)t * 1024 + tid * 4];
        *(float4*)&sX[xi][xj] = xv;
        __syncthreads();

        // phase T
        float t0[4] = {0,0,0,0}, t1[4] = {0,0,0,0};
        #pragma unroll
        for (int i = 0; i < 32; i++) {
            float2 av = *(const float2*)&sAT[i][2 * op];
            float4 hv = *(const float4*)&sX[i][4 * jq];
            t0[0] += av.x*hv.x; t0[1] += av.x*hv.y; t0[2] += av.x*hv.z; t0[3] += av.x*hv.w;
            t1[0] += av.y*hv.x; t1[1] += av.y*hv.y; t1[2] += av.y*hv.z; t1[3] += av.y*hv.w;
        }
        #pragma unroll
        for (int d = 0; d < 4; d++)
            *(float2*)&sTT[4 * jq + d][2 * op] = make_float2(t0[d], t1[d]);
        __syncthreads();

        // phase Y: thread -> o in [8oq,8oq+8), p in {2pp, 2pp+1}
        float y[8][2];
        #pragma unroll
        for (int r = 0; r < 8; r++) { y[r][0] = 0.f; y[r][1] = 0.f; }
        #pragma unroll
        for (int j = 0; j < 32; j++) {
            float2 bv = *(const float2*)&sBT[j][2 * pp];
            float4 ta = *(const float4*)&sTT[j][8 * oq];
            float4 tb = *(const float4*)&sTT[j][8 * oq + 4];
            y[0][0] += ta.x*bv.x; y[0][1] += ta.x*bv.y;
            y[1][0] += ta.y*bv.x; y[1][1] += ta.y*bv.y;
            y[2][0] += ta.z*bv.x; y[2][1] += ta.z*bv.y;
            y[3][0] += ta.w*bv.x; y[3][1] += ta.w*bv.y;
            y[4][0] += tb.x*bv.x; y[4][1] += tb.x*bv.y;
            y[5][0] += tb.y*bv.x; y[5][1] += tb.y*bv.y;
            y[6][0] += tb.z*bv.x; y[6][1] += tb.z*bv.y;
            y[7][0] += tb.w*bv.x; y[7][1] += tb.w*bv.y;
        }
        float* yout = &g_yup[(size_t)pair * 4096];
        #pragma unroll
        for (int r = 0; r < 8; r++)
            *(float2*)&yout[(8 * oq + r) * 64 + 2 * pp] = make_float2(y[r][0], y[r][1]);
        __syncthreads();
    }
}

// ---------------------------------------------------------------------------
// Down bilinear: per pair  T(32x64) = A_e(32x64) H(64x64);  Y(32x32) = T B_e^T
// ---------------------------------------------------------------------------
__global__ __launch_bounds__(256) void bilinear_down(
    const float* __restrict__ A, const float* __restrict__ B)
{
    const int b = blockIdx.x;
    if (b >= g_nchunks) return;
    const int2 ch   = g_chunk[b];
    const int e     = ch.x;
    const int start = ch.y;
    const int cnt   = g_cnt[e];
    const int tid   = threadIdx.x;

    __shared__ float sAT[64][34];   // [i][o]
    __shared__ float sBT[64][34];   // [j][p]
    __shared__ float sH [64][68];   // [i][j]
    __shared__ float sTT[64][36];   // [j][o]

    {   // stage A [32][64] -> sAT, B [32][64] -> sBT (transposed)
        const float4* a4 = (const float4*)(A + (size_t)e * 2048);
        const float4* b4 = (const float4*)(B + (size_t)e * 2048);
        #pragma unroll
        for (int rr = 0; rr < 2; rr++) {
            int f   = tid + 256 * rr;
            int row = f >> 4;            // o or p (<32)
            int col = (f & 15) * 4;      // i or j
            float4 av = a4[f];
            sAT[col+0][row]=av.x; sAT[col+1][row]=av.y; sAT[col+2][row]=av.z; sAT[col+3][row]=av.w;
            float4 bv = b4[f];
            sBT[col+0][row]=bv.x; sBT[col+1][row]=bv.y; sBT[col+2][row]=bv.z; sBT[col+3][row]=bv.w;
        }
    }

    const int op = tid & 15;       // T: o base 2*op
    const int jq = tid >> 4;       // T: j base 4*jq (jq < 16)
    const int pp = tid & 31;       // Y: p = pp
    const int oq = tid >> 5;       // Y: o base 4*oq (warp-uniform)

    __syncthreads();

    for (int u = 0; u < TPB; u++) {
        int pi = start + u;
        if (pi >= cnt) break;
        int pair = g_list[e * NPAIR + pi];
        int t    = pair >> 1;

        const float4* h4 = (const float4*)&g_h[(size_t)t * 4096];
        #pragma unroll
        for (int rr = 0; rr < 4; rr++) {
            int f = tid + 256 * rr;
            *(float4*)&sH[f >> 4][(f & 15) * 4] = h4[f];
        }
        __syncthreads();

        // phase T
        float t0[4] = {0,0,0,0}, t1[4] = {0,0,0,0};
        #pragma unroll
        for (int i = 0; i < 64; i++) {
            float2 av = *(const float2*)&sAT[i][2 * op];
            float4 hv = *(const float4*)&sH[i][4 * jq];
            t0[0] += av.x*hv.x; t0[1] += av.x*hv.y; t0[2] += av.x*hv.z; t0[3] += av.x*hv.w;
            t1[0] += av.y*hv.x; t1[1] += av.y*hv.y; t1[2] += av.y*hv.z; t1[3] += av.y*hv.w;
        }
        #pragma unroll
        for (int d = 0; d < 4; d++)
            *(float2*)&sTT[4 * jq + d][2 * op] = make_float2(t0[d], t1[d]);
        __syncthreads();

        // phase Y: thread -> o in [4oq,4oq+4), p = pp
        float y[4] = {0,0,0,0};
        #pragma unroll
        for (int j = 0; j < 64; j++) {
            float  bv = sBT[j][pp];
            float4 tv = *(const float4*)&sTT[j][4 * oq];
            y[0] += tv.x * bv; y[1] += tv.y * bv; y[2] += tv.z * bv; y[3] += tv.w * bv;
        }
        float* yo = &g_ydown[(size_t)pair * 1024];
        #pragma unroll
        for (int r = 0; r < 4; r++)
            yo[(4 * oq + r) * 32 + pp] = y[r];
        __syncthreads();
    }
}

// ---------------------------------------------------------------------------
// Combine kernels
// ---------------------------------------------------------------------------
__global__ __launch_bounds__(256) void combine_up(
    const float* __restrict__ scale, const float* __restrict__ bias)
{
    const int t   = blockIdx.x;
    const int tid = threadIdx.x;
    const float p0 = g_prob[2 * t], p1 = g_prob[2 * t + 1];
    const float s  = __ldg(scale);
    const float4* y0 = (const float4*)&g_yup[(size_t)(2 * t) * 4096];
    const float4* y1 = (const float4*)&g_yup[(size_t)(2 * t + 1) * 4096];
    const float4* b4 = (const float4*)bias;
    float4* h4 = (float4*)&g_h[(size_t)t * 4096];
    #pragma unroll
    for (int rr = 0; rr < 4; rr++) {
        int f = tid + 256 * rr;
        float4 a = __ldg(&y0[f]), c = __ldg(&y1[f]), bb = __ldg(&b4[f]);
        float4 v;
        v.x = gelu_erf(s * (p0 * a.x + p1 * c.x) + bb.x);
        v.y = gelu_erf(s * (p0 * a.y + p1 * c.y) + bb.y);
        v.z = gelu_erf(s * (p0 * a.z + p1 * c.z) + bb.z);
        v.w = gelu_erf(s * (p0 * a.w + p1 * c.w) + bb.w);
        h4[f] = v;
    }
}

__global__ __launch_bounds__(256) void combine_down(
    const float* __restrict__ scale, const float* __restrict__ bias,
    float* __restrict__ out)
{
    const int t   = blockIdx.x;
    const int tid = threadIdx.x;
    const float p0 = g_prob[2 * t], p1 = g_prob[2 * t + 1];
    const float s  = __ldg(scale);
    const float4* y0 = (const float4*)&g_ydown[(size_t)(2 * t) * 1024];
    const float4* y1 = (const float4*)&g_ydown[(size_t)(2 * t + 1) * 1024];
    const float4* b4 = (const float4*)bias;
    float4 a = __ldg(&y0[tid]), c = __ldg(&y1[tid]), bb = __ldg(&b4[tid]);
    float4 v;
    v.x = s * (p0 * a.x + p1 * c.x) + bb.x;
    v.y = s * (p0 * a.y + p1 * c.y) + bb.y;
    v.z = s * (p0 * a.z + p1 * c.z) + bb.z;
    v.w = s * (p0 * a.w + p1 * c.w) + bb.w;
    ((float4*)&out[(size_t)t * 1024])[tid] = v;
}

// ---------------------------------------------------------------------------
extern "C" void kernel_launch(void* const* d_in, const int* in_sizes, int n_in,
                              void* d_out, int out_size)
{
    const float* x          = (const float*)d_in[0];
    const float* W_up       = (const float*)d_in[1];
    const float* A_up       = (const float*)d_in[2];
    const float* B_up       = (const float*)d_in[3];
    const float* scale_up   = (const float*)d_in[4];
    const float* bias_up    = (const float*)d_in[5];
    const float* W_down     = (const float*)d_in[6];
    const float* A_down     = (const float*)d_in[7];
    const float* B_down     = (const float*)d_in[8];
    const float* scale_down = (const float*)d_in[9];
    const float* bias_down  = (const float*)d_in[10];
    float*       out        = (float*)d_out;

    const int n_tok = in_sizes[0] / 1024;     // 8192

    float* h_ptr = nullptr;
    cudaGetSymbolAddress((void**)&h_ptr, g_h);

    // ---- up ----
    router_gemm<1024><<<n_tok / 64, 256>>>(x, W_up);
    top2_kernel<<<n_tok / 8, 256>>>();
    prefix_kernel<<<1, 64>>>();
    bilinear_up<<<MAXCHUNK, 256>>>(x, A_up, B_up);
    combine_up<<<n_tok, 256>>>(scale_up, bias_up);

    // ---- down ----
    router_gemm<4096><<<n_tok / 64, 256>>>(h_ptr, W_down);
    top2_kernel<<<n_tok / 8, 256>>>();
    prefix_kernel<<<1, 64>>>();
    bilinear_down<<<MAXCHUNK, 256>>>(A_down, B_down);
    combine_down<<<n_tok, 256>>>(scale_down, bias_down, out);
}